// round 5
// baseline (speedup 1.0000x reference)
#include <cuda_runtime.h>
#include <math.h>
#include <float.h>

#define BATCH 8
#define N_X   2048
#define N_L   512
#define DIM   1024
#define NKV   2560   // N_X + N_L
#define HEADS 16
#define DH    64
#define SCALE 0.125f // 64^-0.5

// ---------------- scratch (no allocs allowed) ----------------
__device__ float g_xn[BATCH * N_X * DIM];   // layernormed x
__device__ float g_ln[BATCH * N_L * DIM];   // layernormed latents
__device__ float g_q [BATCH * N_L * DIM];   // q (then rmsnormed in place)
__device__ float g_k [BATCH * NKV * DIM];   // k (concat rows, then rmsnormed)
__device__ float g_v [BATCH * NKV * DIM];   // v (concat rows)
__device__ float g_ao[BATCH * N_L * DIM];   // attention output pre-W_out
__device__ int   g_mask_is_u8;              // 1 if mask stored as 1 byte/elem

// ---------------- mask dtype detection ----------------
// If mask is uint8 (1 byte/elem), bytes at index 4k+1 within the first 16KB
// are random 0/1 -> some nonzero almost surely. If int32/float32 (little
// endian 0/1 values), those bytes are all zero. Safe to read 16KB in every
// case (uint8 buffer is exactly 16384 bytes).
__global__ void detect_mask_kernel(const unsigned char* __restrict__ m) {
    __shared__ int found;
    if (threadIdx.x == 0) found = 0;
    __syncthreads();
    int any = 0;
    for (int k = threadIdx.x; k < 4096; k += 256)
        any |= (m[4 * k + 1] != 0);
    if (any) atomicOr(&found, 1);
    __syncthreads();
    if (threadIdx.x == 0) g_mask_is_u8 = found;
}

// ---------------- layernorm: one block per row ----------------
__global__ void ln_kernel(const float* __restrict__ x,
                          const float* __restrict__ g,
                          const float* __restrict__ b,
                          float* __restrict__ out) {
    int row = blockIdx.x;
    int t = threadIdx.x;
    const float* xr = x + (size_t)row * DIM;
    float v[4];
    float s = 0.f, s2 = 0.f;
#pragma unroll
    for (int k = 0; k < 4; k++) {
        v[k] = xr[t + k * 256];
        s += v[k];
        s2 += v[k] * v[k];
    }
#pragma unroll
    for (int o = 16; o; o >>= 1) {
        s  += __shfl_xor_sync(0xffffffffu, s,  o);
        s2 += __shfl_xor_sync(0xffffffffu, s2, o);
    }
    __shared__ float rs[8], rs2[8];
    __shared__ float smu, srstd;
    int w = t >> 5, l = t & 31;
    if (l == 0) { rs[w] = s; rs2[w] = s2; }
    __syncthreads();
    if (w == 0) {
        s  = (l < 8) ? rs[l]  : 0.f;
        s2 = (l < 8) ? rs2[l] : 0.f;
#pragma unroll
        for (int o = 4; o; o >>= 1) {
            s  += __shfl_xor_sync(0xffffffffu, s,  o);
            s2 += __shfl_xor_sync(0xffffffffu, s2, o);
        }
        if (l == 0) {
            float mu = s * (1.f / DIM);
            float var = s2 * (1.f / DIM) - mu * mu;
            smu = mu;
            srstd = rsqrtf(var + 1e-5f);
        }
    }
    __syncthreads();
    float mu = smu, rstd = srstd;
    float* orow = out + (size_t)row * DIM;
#pragma unroll
    for (int k = 0; k < 4; k++) {
        int c = t + k * 256;
        orow[c] = (v[k] - mu) * rstd * g[c] + b[c];
    }
}

// ---------------- rmsnorm over contiguous 64-vectors, in place ----------------
__global__ void rms_kernel(float* __restrict__ data,
                           const float* __restrict__ gamma,
                           float scale) {
    int vec = blockIdx.x * 8 + (threadIdx.x >> 5);
    int l = threadIdx.x & 31;
    float* p = data + (size_t)vec * 64;
    float a = p[l], b = p[l + 32];
    float ss = a * a + b * b;
#pragma unroll
    for (int o = 16; o; o >>= 1) ss += __shfl_xor_sync(0xffffffffu, ss, o);
    float n = sqrtf(ss) * 0.125f;           // ||x|| / sqrt(64)
    float inv = scale / fmaxf(n, 1e-8f);
    p[l]      = a * inv * gamma[l];
    p[l + 32] = b * inv * gamma[l + 32];
}

// ---------------- SGEMM 128x128x8, 256 threads, 8x8 microtile ----------------
// MODE 0: C0[r*N + c] = acc
// MODE 1: kv scatter: b = r / in_rpb, i = r % in_rpb, orow = b*NKV + row_off + i
//         c < DIM -> C0[orow*DIM + c], else C1[orow*DIM + c - DIM]
// MODE 2: C0[r*N + c] = acc + bias[c]
template <int MODE>
__global__ __launch_bounds__(256)
void gemm_k(const float* __restrict__ A, const float* __restrict__ Bm,
            float* __restrict__ C0, float* __restrict__ C1,
            const float* __restrict__ bias,
            int M, int N, int K, int in_rpb, int row_off) {
    __shared__ float As[8][128];
    __shared__ float Bs[8][128];
    int tid = threadIdx.x;
    int m0 = blockIdx.y * 128, n0 = blockIdx.x * 128;
    int tx = tid & 15, ty = tid >> 4;

    float acc[8][8];
#pragma unroll
    for (int i = 0; i < 8; i++)
#pragma unroll
        for (int j = 0; j < 8; j++) acc[i][j] = 0.f;

    int aRow = tid >> 1, aC4 = (tid & 1) * 4;
    int bRow = tid >> 5, bC4 = (tid & 31) * 4;
    const float* Ap = A + (size_t)(m0 + aRow) * K + aC4;
    const float* Bp = Bm + (size_t)bRow * N + n0 + bC4;

    for (int k0 = 0; k0 < K; k0 += 8) {
        float4 a4 = *(const float4*)(Ap + k0);
        float4 b4 = *(const float4*)(Bp + (size_t)k0 * N);
        As[aC4 + 0][aRow] = a4.x;
        As[aC4 + 1][aRow] = a4.y;
        As[aC4 + 2][aRow] = a4.z;
        As[aC4 + 3][aRow] = a4.w;
        *(float4*)&Bs[bRow][bC4] = b4;
        __syncthreads();
#pragma unroll
        for (int kk = 0; kk < 8; kk++) {
            float af[8], bf[8];
            *(float4*)(af)     = *(const float4*)&As[kk][ty * 8];
            *(float4*)(af + 4) = *(const float4*)&As[kk][ty * 8 + 4];
            *(float4*)(bf)     = *(const float4*)&Bs[kk][tx * 8];
            *(float4*)(bf + 4) = *(const float4*)&Bs[kk][tx * 8 + 4];
#pragma unroll
            for (int i = 0; i < 8; i++)
#pragma unroll
                for (int j = 0; j < 8; j++)
                    acc[i][j] += af[i] * bf[j];
        }
        __syncthreads();
    }

#pragma unroll
    for (int i = 0; i < 8; i++) {
        int r = m0 + ty * 8 + i;
        size_t orow = 0;
        if (MODE == 1) {
            int bb = r / in_rpb;
            int ii = r - bb * in_rpb;
            orow = (size_t)bb * NKV + row_off + ii;
        }
#pragma unroll
        for (int j = 0; j < 8; j++) {
            int c = n0 + tx * 8 + j;
            float val = acc[i][j];
            if (MODE == 0) {
                C0[(size_t)r * N + c] = val;
            } else if (MODE == 1) {
                if (c < DIM) C0[orow * DIM + c] = val;
                else         C1[orow * DIM + (c - DIM)] = val;
            } else {
                C0[(size_t)r * N + c] = val + bias[c];
            }
        }
    }
}

// ---------------- flash attention: 1 thread = 1 query row ----------------
// grid (8 q-tiles, 16 heads, 8 batches), 64 threads
__global__ __launch_bounds__(64)
void attn_kernel(const float* __restrict__ q, const float* __restrict__ kmat,
                 const float* __restrict__ vmat,
                 const void* __restrict__ mask_raw,
                 float* __restrict__ out) {
    __shared__ float ks[32][68];
    __shared__ float vs[32][68];
    __shared__ float ssm[64][33];
    __shared__ float mflag[32];   // 1.0 = masked out

    int t = threadIdx.x;
    int h = blockIdx.y, bb = blockIdx.z;
    int i = blockIdx.x * 64 + t;
    int mask_u8 = g_mask_is_u8;
    const unsigned char* mask8 = (const unsigned char*)mask_raw;
    const int* mask32 = (const int*)mask_raw;

    const float* qp = q + (size_t)(bb * N_L + i) * DIM + h * DH;
    float qr[64];
#pragma unroll
    for (int d4 = 0; d4 < 16; d4++) {
        float4 f = *(const float4*)(qp + d4 * 4);
        qr[d4 * 4 + 0] = f.x; qr[d4 * 4 + 1] = f.y;
        qr[d4 * 4 + 2] = f.z; qr[d4 * 4 + 3] = f.w;
    }
    float o[64];
#pragma unroll
    for (int d = 0; d < 64; d++) o[d] = 0.f;
    float m = -1e30f, l = 0.f;

    for (int j0 = 0; j0 < NKV; j0 += 32) {
        __syncthreads();
        if (t < 32) {
            int j = j0 + t;
            const float* kp = kmat + (size_t)(bb * NKV + j) * DIM + h * DH;
#pragma unroll
            for (int d4 = 0; d4 < 16; d4++) {
                float4 f = *(const float4*)(kp + d4 * 4);
                ks[t][d4 * 4 + 0] = f.x; ks[t][d4 * 4 + 1] = f.y;
                ks[t][d4 * 4 + 2] = f.z; ks[t][d4 * 4 + 3] = f.w;
            }
            int valid;
            if (j >= N_X) valid = 1;
            else if (mask_u8) valid = (mask8[bb * N_X + j] != 0);
            else valid = (mask32[bb * N_X + j] != 0);
            mflag[t] = valid ? 0.f : 1.f;
        } else {
            int j = j0 + (t - 32);
            const float* vp = vmat + (size_t)(bb * NKV + j) * DIM + h * DH;
            int tr = t - 32;
#pragma unroll
            for (int d4 = 0; d4 < 16; d4++) {
                float4 f = *(const float4*)(vp + d4 * 4);
                vs[tr][d4 * 4 + 0] = f.x; vs[tr][d4 * 4 + 1] = f.y;
                vs[tr][d4 * 4 + 2] = f.z; vs[tr][d4 * 4 + 3] = f.w;
            }
        }
        __syncthreads();

        float cmax = -FLT_MAX;
#pragma unroll 4
        for (int jj = 0; jj < 32; jj++) {
            float s = 0.f;
#pragma unroll
            for (int d = 0; d < 64; d += 4) {
                float4 kf = *(const float4*)&ks[jj][d];
                s += qr[d] * kf.x + qr[d + 1] * kf.y
                   + qr[d + 2] * kf.z + qr[d + 3] * kf.w;
            }
            s = (mflag[jj] != 0.f) ? -FLT_MAX : s;
            ssm[t][jj] = s;
            cmax = fmaxf(cmax, s);
        }
        float mnew = fmaxf(m, cmax);
        float alpha = __expf(m - mnew);
        l *= alpha;
#pragma unroll
        for (int d = 0; d < 64; d++) o[d] *= alpha;
#pragma unroll 4
        for (int jj = 0; jj < 32; jj++) {
            float p = __expf(ssm[t][jj] - mnew);
            l += p;
#pragma unroll
            for (int d = 0; d < 64; d += 4) {
                float4 vf = *(const float4*)&vs[jj][d];
                o[d]     += p * vf.x;
                o[d + 1] += p * vf.y;
                o[d + 2] += p * vf.z;
                o[d + 3] += p * vf.w;
            }
        }
        m = mnew;
    }

    float invl = 1.f / l;
    float* op = out + (size_t)(bb * N_L + i) * DIM + h * DH;
#pragma unroll
    for (int d4 = 0; d4 < 16; d4++) {
        float4 f;
        f.x = o[d4 * 4 + 0] * invl;
        f.y = o[d4 * 4 + 1] * invl;
        f.z = o[d4 * 4 + 2] * invl;
        f.w = o[d4 * 4 + 3] * invl;
        *(float4*)(op + d4 * 4) = f;
    }
}

// ---------------- launch ----------------
extern "C" void kernel_launch(void* const* d_in, const int* in_sizes, int n_in,
                              void* d_out, int out_size) {
    const float* x        = (const float*)d_in[0];
    const float* latents  = (const float*)d_in[1];
    const void*  mask     = d_in[2];
    const float* ln_x_g   = (const float*)d_in[3];
    const float* ln_x_b   = (const float*)d_in[4];
    const float* ln_l_g   = (const float*)d_in[5];
    const float* ln_l_b   = (const float*)d_in[6];
    const float* q_gamma  = (const float*)d_in[7];
    const float* k_gamma  = (const float*)d_in[8];
    const float* W_q      = (const float*)d_in[9];
    const float* W_kv     = (const float*)d_in[10];
    const float* W_out    = (const float*)d_in[11];
    const float* b_out    = (const float*)d_in[12];
    float* out = (float*)d_out;

    void *p_xn, *p_ln, *p_q, *p_k, *p_v, *p_ao;
    cudaGetSymbolAddress(&p_xn, g_xn);
    cudaGetSymbolAddress(&p_ln, g_ln);
    cudaGetSymbolAddress(&p_q,  g_q);
    cudaGetSymbolAddress(&p_k,  g_k);
    cudaGetSymbolAddress(&p_v,  g_v);
    cudaGetSymbolAddress(&p_ao, g_ao);
    float* xn = (float*)p_xn;
    float* ln = (float*)p_ln;
    float* q  = (float*)p_q;
    float* k  = (float*)p_k;
    float* v  = (float*)p_v;
    float* ao = (float*)p_ao;

    // 0. detect mask dtype (uint8 vs int32/float32)
    detect_mask_kernel<<<1, 256>>>((const unsigned char*)mask);

    // 1. layernorms
    ln_kernel<<<BATCH * N_X, 256>>>(x, ln_x_g, ln_x_b, xn);
    ln_kernel<<<BATCH * N_L, 256>>>(latents, ln_l_g, ln_l_b, ln);

    // 2. q = ln @ W_q   (4096 x 1024 x 1024)
    gemm_k<0><<<dim3(1024 / 128, (BATCH * N_L) / 128), 256>>>(
        ln, W_q, q, nullptr, nullptr, BATCH * N_L, 1024, 1024, 0, 0);

    // 3. kv from xn (16384 x 2048 x 1024) and from ln (4096 x 2048 x 1024)
    gemm_k<1><<<dim3(2048 / 128, (BATCH * N_X) / 128), 256>>>(
        xn, W_kv, k, v, nullptr, BATCH * N_X, 2048, 1024, N_X, 0);
    gemm_k<1><<<dim3(2048 / 128, (BATCH * N_L) / 128), 256>>>(
        ln, W_kv, k, v, nullptr, BATCH * N_L, 2048, 1024, N_L, N_X);

    // 4. rmsnorms (in place), q also * SCALE
    rms_kernel<<<(BATCH * N_L * HEADS) / 8, 256>>>(q, q_gamma, SCALE);
    rms_kernel<<<(BATCH * NKV * HEADS) / 8, 256>>>(k, k_gamma, 1.0f);

    // 5. attention
    attn_kernel<<<dim3(N_L / 64, HEADS, BATCH), 64>>>(q, k, v, mask, ao);

    // 6. out = ao @ W_out + b_out
    gemm_k<2><<<dim3(1024 / 128, (BATCH * N_L) / 128), 256>>>(
        ao, W_out, out, nullptr, b_out, BATCH * N_L, 1024, 1024, 0, 0);
}